// round 7
// baseline (speedup 1.0000x reference)
#include <cuda_runtime.h>
#include <mma.h>
#include <cstdint>
#include <math.h>

using namespace nvcuda;

// ---------------- problem constants ----------------
#define BNB   650
#define TT    48
#define T2    12
#define VV    3
#define CC    128
#define DIN   387
#define EVLD  388
#define HD    512
#define HH    8
#define DD    64
#define LL    4
#define NB    6
#define NHID  4
#define CY    515
#define INLD  516
#define ROWS  (BNB*T2)     // 7800
#define KVROWS (BNB*TT)    // 31200
#define LOG2PI 1.8378770664093453f

// ---------------- scratch ----------------
__device__ float g_ev[BNB*TT*EVLD];
__device__ float g_wk[LL*DIN*HD];
__device__ float g_wv[LL*DIN*HD];
__device__ float g_wshift[384*HD];
__device__ float g_ffw1[LL*HD*HD];
__device__ float g_ffw2[LL*HD*HD];
__device__ float g_keys[LL*KVROWS*HD];
__device__ float g_vals[LL*KVROWS*HD];
__device__ float g_attin[ROWS*384];
__device__ float g_attv[ROWS*HD];
__device__ float g_attbuf[ROWS*HD];
__device__ float g_f1[ROWS*HD];
__device__ float g_f2[ROWS*HD];
__device__ float g_inp[ROWS*INLD];
__device__ float g_hA[2*ROWS*HD];
__device__ float g_hB[2*ROWS*HD];
__device__ float g_u[ROWS*VV];
__device__ float g_ld[ROWS*VV];
__device__ float g_stats[2*T2*VV];
__device__ float g_win[NB*2*CY*HD];
__device__ float g_bin[NB*2*HD];
__device__ float g_whid[NB*NHID*2*HD*HD];
__device__ float g_bhid[NB*NHID*2*HD];

// round-to-nearest tf32 (HMMA truncation is exact afterwards)
__device__ __forceinline__ float to_tf32(float x) {
    float y;
    asm("cvt.rna.tf32.f32 %0, %1;" : "=f"(y) : "f"(x));
    return y;
}
// HW tanh approx (MUFU) — rel err ~2^-11, same scale as tf32 quantization
__device__ __forceinline__ float fast_tanh(float x) {
    float y;
    asm("tanh.approx.f32 %0, %1;" : "=f"(y) : "f"(x));
    return y;
}

__device__ __forceinline__ float epi_act(float v, int act) {
    if (act == 1) return fmaxf(v, 0.f);
    if (act == 2) return fast_tanh(v);
    return v;
}

__device__ __forceinline__ void cpa16(uint32_t dst, const float* src, int sz) {
    asm volatile("cp.async.cg.shared.global [%0], [%1], 16, %2;"
                 :: "r"(dst), "l"(src), "r"(sz));
}
__device__ __forceinline__ void cpa_commit() {
    asm volatile("cp.async.commit_group;" ::: "memory");
}

// ---------- wmma tf32 GEMM: 256 thr, CTA 128x256, 8 warps of 64x64 --------
// 4-stage cp.async pipeline; epilogue staged in two 64-row half-bands.
#define ALD 36
#define BLD 260
#define CLD 260
#define A_STG (128*ALD)               // 4608 floats
#define B_STG (32*BLD)                // 8320 floats
#define STG   (A_STG + B_STG)         // 12928 floats = 51712 B
#define NSTAGE 4
#define WM_SMEM (NSTAGE*STG*4)        // 206848 B

__global__ __launch_bounds__(256, 1) void wmma_gemm(
    const float* __restrict__ A, int lda, long long sA,
    const float* __restrict__ B, const float* __restrict__ bias,
    float* __restrict__ C,
    int M, int N, int Kpad, int Kreal, int act0, int act1,
    long long sB, long long sBias, long long sC)
{
    extern __shared__ float sm[];
    long long z = blockIdx.z;
    A    += z * sA;
    B    += z * sB;
    bias += z * sBias;
    C    += z * sC;
    int act = (z == 0) ? act0 : act1;

    int bm = blockIdx.x * 128, bn = blockIdx.y * 256;
    int tid = threadIdx.x, wid = tid >> 5;
    int warp_m = wid >> 2, warp_n = wid & 3;   // 2x4 warps of 64x64

    wmma::fragment<wmma::accumulator, 16, 16, 8, float> acc[4][4];
    #pragma unroll
    for (int i = 0; i < 4; i++)
        #pragma unroll
        for (int j = 0; j < 4; j++) wmma::fill_fragment(acc[i][j], 0.f);

    int nch = (Kpad + 31) >> 5;

    auto load_stage = [&](int s, int c) {
        uint32_t base = (uint32_t)__cvta_generic_to_shared(sm + s * STG);
        uint32_t bBase = base + A_STG * 4;
        int k0 = c << 5;
        // A: 128 x 32 = 1024 float4
        #pragma unroll
        for (int it = 0; it < 4; it++) {
            int q = it * 256 + tid;
            int r = q >> 3, kk = (q & 7) << 2;
            int gm = bm + r, gk = k0 + kk;
            int ok = (gm < M && gk < Kpad);
            int cgm = ok ? gm : 0, cgk = ok ? gk : 0;
            cpa16(base + (uint32_t)(r * ALD + kk) * 4,
                  A + (long long)cgm * lda + cgk, ok ? 16 : 0);
        }
        // B: 32 x 256 = 2048 float4
        #pragma unroll
        for (int it = 0; it < 8; it++) {
            int q = it * 256 + tid;
            int kk = q >> 6, n = (q & 63) << 2;
            int gk = k0 + kk;
            int ok = (gk < Kreal);
            int cgk = ok ? gk : 0;
            cpa16(bBase + (uint32_t)(kk * BLD + n) * 4,
                  B + (long long)cgk * N + bn + n, ok ? 16 : 0);
        }
    };

    // prologue: prefetch up to 3 stages
    #pragma unroll
    for (int p = 0; p < 3; p++) {
        if (p < nch) { load_stage(p, p); cpa_commit(); }
    }

    for (int c = 0; c < nch; c++) {
        int rem = nch - 1 - c;
        if (rem >= 2)      asm volatile("cp.async.wait_group 2;" ::: "memory");
        else if (rem == 1) asm volatile("cp.async.wait_group 1;" ::: "memory");
        else               asm volatile("cp.async.wait_group 0;" ::: "memory");
        __syncthreads();
        if (c + 3 < nch) { load_stage((c + 3) & 3, c + 3); cpa_commit(); }

        float* As = sm + (c & 3) * STG;
        float* Bs = As + A_STG;
        #pragma unroll
        for (int ks = 0; ks < 4; ks++) {
            int k0 = ks * 8;
            wmma::fragment<wmma::matrix_a, 16, 16, 8, wmma::precision::tf32, wmma::row_major> af[4];
            wmma::fragment<wmma::matrix_b, 16, 16, 8, wmma::precision::tf32, wmma::row_major> bf[4];
            #pragma unroll
            for (int i = 0; i < 4; i++)
                wmma::load_matrix_sync(af[i], As + (warp_m*64 + i*16) * ALD + k0, ALD);
            #pragma unroll
            for (int j = 0; j < 4; j++)
                wmma::load_matrix_sync(bf[j], Bs + k0 * BLD + warp_n*64 + j*16, BLD);
            #pragma unroll
            for (int i = 0; i < 4; i++)
                #pragma unroll
                for (int j = 0; j < 4; j++)
                    wmma::mma_sync(acc[i][j], af[i], bf[j], acc[i][j]);
        }
    }
    __syncthreads();

    // epilogue: two 64-row half-bands staged through SMEM
    float* Cs = sm;
    #pragma unroll
    for (int p = 0; p < 2; p++) {
        if (warp_m == p) {
            #pragma unroll
            for (int i = 0; i < 4; i++)
                #pragma unroll
                for (int j = 0; j < 4; j++)
                    wmma::store_matrix_sync(Cs + (i*16) * CLD + warp_n*64 + j*16,
                                            acc[i][j], CLD, wmma::mem_row_major);
        }
        __syncthreads();
        #pragma unroll
        for (int it = 0; it < 16; it++) {
            int idx = it * 256 + tid;
            int r = idx >> 6, c4 = (idx & 63) * 4;
            int gm = bm + p * 64 + r;
            if (gm < M) {
                int gc = bn + c4;
                float4 v;
                v.x = to_tf32(epi_act(Cs[r * CLD + c4 + 0] + bias[gc + 0], act));
                v.y = to_tf32(epi_act(Cs[r * CLD + c4 + 1] + bias[gc + 1], act));
                v.z = to_tf32(epi_act(Cs[r * CLD + c4 + 2] + bias[gc + 2], act));
                v.w = to_tf32(epi_act(Cs[r * CLD + c4 + 3] + bias[gc + 3], act));
                *(float4*)(C + (long long)gm * N + gc) = v;
            }
        }
        __syncthreads();
    }
}

// ---------------- pack / round kernels ----------------
__global__ void roundcopy_kernel(const float* __restrict__ src, float* __restrict__ dst,
                                 long long n)
{
    long long idx = (long long)blockIdx.x * blockDim.x + threadIdx.x;
    if (idx < n) dst[idx] = to_tf32(src[idx]);
}
__global__ void pack_win_kernel(const float* __restrict__ s, const float* __restrict__ t)
{
    int idx = blockIdx.x * blockDim.x + threadIdx.x;
    const int per = CY*HD;
    if (idx >= NB*2*per) return;
    int blk = idx / (2*per);
    int r = idx - blk*2*per;
    int net = r / per, off = r - net*per;
    g_win[idx] = to_tf32(net ? t[(long long)blk*per + off] : s[(long long)blk*per + off]);
}
__global__ void pack_bin_kernel(const float* __restrict__ s, const float* __restrict__ t)
{
    int idx = blockIdx.x * blockDim.x + threadIdx.x;
    if (idx >= NB*2*HD) return;
    int blk = idx / (2*HD);
    int r = idx - blk*2*HD;
    int net = r / HD, off = r - net*HD;
    g_bin[idx] = net ? t[blk*HD + off] : s[blk*HD + off];
}
__global__ void pack_whid_kernel(const float* __restrict__ s, const float* __restrict__ t)
{
    long long idx = (long long)blockIdx.x * blockDim.x + threadIdx.x;
    const long long per = HD*HD;
    if (idx >= (long long)NB*NHID*2*per) return;
    long long u = idx / (2*per);
    long long r = idx - u*2*per;
    int net = (int)(r / per);
    long long off = r - (long long)net*per;
    g_whid[idx] = to_tf32(net ? t[u*per + off] : s[u*per + off]);
}
__global__ void pack_bhid_kernel(const float* __restrict__ s, const float* __restrict__ t)
{
    int idx = blockIdx.x * blockDim.x + threadIdx.x;
    if (idx >= NB*NHID*2*HD) return;
    int u = idx / (2*HD);
    int r = idx - u*2*HD;
    int net = r / HD, off = r - net*HD;
    g_bhid[idx] = net ? t[u*HD + off] : s[u*HD + off];
}

// ---------------- small kernels ----------------
__global__ void transpose_w_kernel(const float* __restrict__ W, float* __restrict__ out)
{
    int idx = blockIdx.x * blockDim.x + threadIdx.x;
    if (idx >= LL*DIN*HD) return;
    int l = idx / (DIN*HD);
    int rem = idx - l * (DIN*HD);
    int e = rem / HD;
    int n = rem - e * HD;
    int h = n >> 6, d = n & 63;
    out[idx] = to_tf32(W[(((long long)l*HH + h)*DIN + e)*DD + d]);
}

__global__ void build_ev_kernel(const float* __restrict__ encoded,
                                const float* __restrict__ tv)
{
    int idx = blockIdx.x * blockDim.x + threadIdx.x;
    if (idx >= BNB*TT*EVLD) return;
    int bn = idx / (TT*EVLD);
    int rem = idx - bn * (TT*EVLD);
    int t = rem / EVLD;
    int e = rem - t * EVLD;
    float val = 0.f;
    if (e < DIN) {
        int v = e / (CC+1);
        int j = e - v * (CC+1);
        if (j < CC) val = encoded[(((long long)bn*VV + v)*TT + t)*CC + j];
        else        val = tv[((long long)bn*VV + v)*TT + t];
    }
    g_ev[idx] = to_tf32(val);
}

__global__ void build_attin_kernel(const float* __restrict__ encoded)
{
    int idx = blockIdx.x * blockDim.x + threadIdx.x;
    if (idx >= ROWS*384) return;
    int row = idx / 384;
    int col = idx - row*384;
    int bn = row / T2, t2 = row - bn*T2;
    int v = col >> 7, j = col & 127;
    g_attin[idx] = to_tf32(encoded[(((long long)bn*VV + v)*TT + (TT - T2 + t2))*CC + j]);
}

__global__ void attn_kernel(const float* __restrict__ attv,
                            const float* __restrict__ keys_l,
                            const float* __restrict__ vals_l,
                            float* __restrict__ attbuf)
{
    int bn = blockIdx.x, h = blockIdx.y;
    __shared__ float Qs[T2*DD];
    __shared__ float Ks[TT*DD];
    __shared__ float Vs[TT*DD];
    __shared__ float Ss[T2*TT];
    int tid = threadIdx.x;
    const float* kb = keys_l + (long long)bn*TT*HD + h*DD;
    const float* vb = vals_l + (long long)bn*TT*HD + h*DD;
    for (int i = tid; i < TT*DD; i += 256) {
        int t = i >> 6, d = i & 63;
        Ks[i] = kb[(long long)t*HD + d];
        Vs[i] = vb[(long long)t*HD + d];
    }
    for (int i = tid; i < T2*DD; i += 256) {
        int v = i >> 6, d = i & 63;
        Qs[i] = attv[((long long)bn*T2 + v)*HD + h*DD + d];
    }
    __syncthreads();
    const float scale = 0.125f;
    for (int i = tid; i < T2*TT; i += 256) {
        int v = i / TT, w = i - v*TT;
        float s;
        if (w >= (TT - T2) + v) s = -INFINITY;
        else {
            float a = 0.f;
            #pragma unroll
            for (int d = 0; d < DD; d++) a += Qs[v*DD+d] * Ks[w*DD+d];
            s = a * scale;
        }
        Ss[i] = s;
    }
    __syncthreads();
    if (tid < T2) {
        int v = tid;
        float m = -INFINITY;
        for (int w = 0; w < TT; w++) m = fmaxf(m, Ss[v*TT+w]);
        float sum = 0.f;
        for (int w = 0; w < TT; w++) {
            float e = expf(Ss[v*TT+w] - m);
            Ss[v*TT+w] = e; sum += e;
        }
        float inv = 1.f / sum;
        for (int w = 0; w < TT; w++) Ss[v*TT+w] *= inv;
    }
    __syncthreads();
    for (int i = tid; i < T2*DD; i += 256) {
        int v = i >> 6, d = i & 63;
        float a = 0.f;
        #pragma unroll
        for (int w = 0; w < TT; w++) a += Ss[v*TT+w] * Vs[w*DD+d];
        attbuf[((long long)bn*T2 + v)*HD + h*DD + d] = a;
    }
}

__global__ void add_ln_kernel(float* __restrict__ x, const float* __restrict__ r,
                              const float* __restrict__ g, const float* __restrict__ b)
{
    int row = blockIdx.x;
    int tid = threadIdx.x;
    __shared__ float red[256];
    long long base = (long long)row * HD;
    float v0 = x[base + tid] + r[base + tid];
    float v1 = x[base + tid + 256] + r[base + tid + 256];
    red[tid] = v0 + v1;
    __syncthreads();
    for (int s = 128; s > 0; s >>= 1) { if (tid < s) red[tid] += red[tid+s]; __syncthreads(); }
    float mean = red[0] * (1.f/512.f);
    __syncthreads();
    float d0 = v0 - mean, d1 = v1 - mean;
    red[tid] = d0*d0 + d1*d1;
    __syncthreads();
    for (int s = 128; s > 0; s >>= 1) { if (tid < s) red[tid] += red[tid+s]; __syncthreads(); }
    float rstd = rsqrtf(red[0] * (1.f/512.f) + 1e-5f);
    x[base + tid]       = to_tf32(d0 * rstd * g[tid]       + b[tid]);
    x[base + tid + 256] = to_tf32(d1 * rstd * g[tid + 256] + b[tid + 256]);
}

__global__ void init_flow_kernel(const float* __restrict__ tv)
{
    int idx = blockIdx.x * blockDim.x + threadIdx.x;
    if (idx >= ROWS*VV) return;
    int bn = idx / (T2*VV);
    int rem = idx - bn * (T2*VV);
    int t2 = rem / VV, v = rem - t2*VV;
    g_u[idx] = tv[((long long)bn*VV + v)*TT + (TT - T2 + t2)];
    g_ld[idx] = 0.f;
}

__global__ void copy_y_kernel()
{
    int idx = blockIdx.x * blockDim.x + threadIdx.x;
    if (idx >= ROWS*INLD) return;
    int row = idx / INLD, col = idx - row*INLD;
    if (col < HD)        g_inp[idx] = g_attv[(long long)row*HD + col];
    else if (col == 515) g_inp[idx] = 0.f;
}

__global__ void write_mu_kernel(int blk)
{
    int idx = blockIdx.x * blockDim.x + threadIdx.x;
    if (idx >= ROWS*VV) return;
    int row = idx / VV, v = idx - row*VV;
    float mask = (float)((v + blk) & 1);
    g_inp[(long long)row * INLD + HD + v] = to_tf32(g_u[idx] * mask);
}

__global__ void out3_coupling_kernel(const float* __restrict__ h,
                                     const float* __restrict__ Ws, const float* __restrict__ bs,
                                     const float* __restrict__ Wt, const float* __restrict__ bt,
                                     int blk)
{
    int gw = (blockIdx.x * blockDim.x + threadIdx.x) >> 5;
    int lane = threadIdx.x & 31;
    if (gw >= ROWS) return;
    const float* as = h + (long long)gw * HD;
    const float* at = h + (long long)ROWS*HD + (long long)gw * HD;
    float s0 = 0.f, s1 = 0.f, s2 = 0.f, t0 = 0.f, t1 = 0.f, t2 = 0.f;
    for (int k = lane; k < HD; k += 32) {
        float av = as[k], bv = at[k];
        s0 += av * Ws[k*3 + 0]; s1 += av * Ws[k*3 + 1]; s2 += av * Ws[k*3 + 2];
        t0 += bv * Wt[k*3 + 0]; t1 += bv * Wt[k*3 + 1]; t2 += bv * Wt[k*3 + 2];
    }
    #pragma unroll
    for (int off = 16; off > 0; off >>= 1) {
        s0 += __shfl_down_sync(0xffffffffu, s0, off);
        s1 += __shfl_down_sync(0xffffffffu, s1, off);
        s2 += __shfl_down_sync(0xffffffffu, s2, off);
        t0 += __shfl_down_sync(0xffffffffu, t0, off);
        t1 += __shfl_down_sync(0xffffffffu, t1, off);
        t2 += __shfl_down_sync(0xffffffffu, t2, off);
    }
    if (lane == 0) {
        float sv[3] = {s0 + bs[0], s1 + bs[1], s2 + bs[2]};
        float tv[3] = {t0 + bt[0], t1 + bt[1], t2 + bt[2]};
        #pragma unroll
        for (int v = 0; v < VV; v++) {
            if (((v + blk) & 1) == 0) {
                int idx = gw*3 + v;
                float s = sv[v];
                g_u[idx]  = (g_u[idx] - tv[v]) * expf(-s);
                g_ld[idx] -= s;
            }
        }
    }
}

__global__ void bn_stats_kernel()
{
    int col = blockIdx.x;
    int tid = threadIdx.x;
    __shared__ float rs[256], rq[256];
    float s = 0.f, q = 0.f;
    for (int bn = tid; bn < BNB; bn += 256) {
        float v = g_u[bn*(T2*VV) + col];
        s += v; q += v*v;
    }
    rs[tid] = s; rq[tid] = q;
    __syncthreads();
    for (int st = 128; st > 0; st >>= 1) {
        if (tid < st) { rs[tid] += rs[tid+st]; rq[tid] += rq[tid+st]; }
        __syncthreads();
    }
    if (tid == 0) {
        float m = rs[0] / (float)BNB;
        float var = rq[0] / (float)BNB - m*m;
        g_stats[col] = m;
        g_stats[T2*VV + col] = fmaxf(var, 0.f);
    }
}

__global__ void bn_apply_kernel(const float* __restrict__ lg,
                                const float* __restrict__ beta, int blk, int write_next)
{
    int idx = blockIdx.x * blockDim.x + threadIdx.x;
    if (idx >= ROWS*VV) return;
    int col = idx % (T2*VV);
    int v = idx % VV;
    float m = g_stats[col];
    float var = g_stats[T2*VV + col];
    float gg = lg[blk*VV + v];
    float be = beta[blk*VV + v];
    float r = rsqrtf(var + 1e-5f);
    float u = expf(gg) * (g_u[idx] - m) * r + be;
    g_u[idx] = u;
    g_ld[idx] += gg - 0.5f * logf(var + 1e-5f);
    if (write_next) {
        float mask = (float)((v + blk + 1) & 1);
        g_inp[(long long)(idx / VV) * INLD + HD + v] = to_tf32(u * mask);
    }
}

__global__ void final_kernel(float* __restrict__ out)
{
    int bn = blockIdx.x * blockDim.x + threadIdx.x;
    if (bn >= BNB) return;
    float acc = 0.f;
    #pragma unroll
    for (int i = 0; i < T2*VV; i++) {
        float u = g_u[bn*(T2*VV) + i];
        acc += 0.5f*u*u + 0.5f*LOG2PI - g_ld[bn*(T2*VV) + i];
    }
    out[bn] = acc;
}

// ---------------- host launcher ----------------
static inline void tcg(const float* A, int lda, long long sA,
                       const float* B, const float* bias, float* C,
                       int M, int N, int Kpad, int Kreal, int act0, int act1,
                       long long sB, long long sBias, long long sC, int Z)
{
    dim3 grid((M + 127)/128, N/256, Z);
    wmma_gemm<<<grid, 256, WM_SMEM>>>(A, lda, sA, B, bias, C,
                                      M, N, Kpad, Kreal, act0, act1, sB, sBias, sC);
}

extern "C" void kernel_launch(void* const* d_in, const int* in_sizes, int n_in,
                              void* d_out, int out_size)
{
    const float* encoded    = (const float*)d_in[0];
    const float* true_value = (const float*)d_in[1];
    const float* W_shift    = (const float*)d_in[2];
    const float* b_shift    = (const float*)d_in[3];
    const float* W_key      = (const float*)d_in[4];
    const float* b_key      = (const float*)d_in[5];
    const float* W_val      = (const float*)d_in[6];
    const float* b_val      = (const float*)d_in[7];
    const float* ln1_s      = (const float*)d_in[8];
    const float* ln1_b      = (const float*)d_in[9];
    const float* ff_w1      = (const float*)d_in[10];
    const float* ff_b1      = (const float*)d_in[11];
    const float* ff_w2      = (const float*)d_in[12];
    const float* ff_b2      = (const float*)d_in[13];
    const float* ln2_s      = (const float*)d_in[14];
    const float* ln2_b      = (const float*)d_in[15];
    const float* s_w_in     = (const float*)d_in[16];
    const float* s_b_in     = (const float*)d_in[17];
    const float* s_w_hid    = (const float*)d_in[18];
    const float* s_b_hid    = (const float*)d_in[19];
    const float* s_w_out    = (const float*)d_in[20];
    const float* s_b_out    = (const float*)d_in[21];
    const float* t_w_in     = (const float*)d_in[22];
    const float* t_b_in     = (const float*)d_in[23];
    const float* t_w_hid    = (const float*)d_in[24];
    const float* t_b_hid    = (const float*)d_in[25];
    const float* t_w_out    = (const float*)d_in[26];
    const float* t_b_out    = (const float*)d_in[27];
    const float* bn_lg      = (const float*)d_in[28];
    const float* bn_be      = (const float*)d_in[29];
    float* out = (float*)d_out;

    cudaFuncSetAttribute(wmma_gemm, cudaFuncAttributeMaxDynamicSharedMemorySize, WM_SMEM);

    float *ev, *wk, *wv, *wshift, *ffw1, *ffw2, *keys, *vals, *attin, *attv, *attbuf, *f1, *f2, *inp;
    float *hA, *hB, *win, *bin, *whid, *bhid;
    cudaGetSymbolAddress((void**)&ev,     g_ev);
    cudaGetSymbolAddress((void**)&wk,     g_wk);
    cudaGetSymbolAddress((void**)&wv,     g_wv);
    cudaGetSymbolAddress((void**)&wshift, g_wshift);
    cudaGetSymbolAddress((void**)&ffw1,   g_ffw1);
    cudaGetSymbolAddress((void**)&ffw2,   g_ffw2);
    cudaGetSymbolAddress((void**)&keys,   g_keys);
    cudaGetSymbolAddress((void**)&vals,   g_vals);
    cudaGetSymbolAddress((void**)&attin,  g_attin);
    cudaGetSymbolAddress((void**)&attv,   g_attv);
    cudaGetSymbolAddress((void**)&attbuf, g_attbuf);
    cudaGetSymbolAddress((void**)&f1,     g_f1);
    cudaGetSymbolAddress((void**)&f2,     g_f2);
    cudaGetSymbolAddress((void**)&inp,    g_inp);
    cudaGetSymbolAddress((void**)&hA,     g_hA);
    cudaGetSymbolAddress((void**)&hB,     g_hB);
    cudaGetSymbolAddress((void**)&win,    g_win);
    cudaGetSymbolAddress((void**)&bin,    g_bin);
    cudaGetSymbolAddress((void**)&whid,   g_whid);
    cudaGetSymbolAddress((void**)&bhid,   g_bhid);

    {
        int n = LL*DIN*HD;
        transpose_w_kernel<<<(n + 255)/256, 256>>>(W_key, wk);
        transpose_w_kernel<<<(n + 255)/256, 256>>>(W_val, wv);
        long long nw = 384*HD;
        roundcopy_kernel<<<(int)((nw + 255)/256), 256>>>(W_shift, wshift, nw);
        long long nf = (long long)LL*HD*HD;
        roundcopy_kernel<<<(int)((nf + 255)/256), 256>>>(ff_w1, ffw1, nf);
        roundcopy_kernel<<<(int)((nf + 255)/256), 256>>>(ff_w2, ffw2, nf);
        int m = BNB*TT*EVLD;
        build_ev_kernel<<<(m + 255)/256, 256>>>(encoded, true_value);
        int q = ROWS*384;
        build_attin_kernel<<<(q + 255)/256, 256>>>(encoded);
        int p1 = NB*2*CY*HD;
        pack_win_kernel<<<(p1 + 255)/256, 256>>>(s_w_in, t_w_in);
        int p2 = NB*2*HD;
        pack_bin_kernel<<<(p2 + 255)/256, 256>>>(s_b_in, t_b_in);
        long long p3 = (long long)NB*NHID*2*HD*HD;
        pack_whid_kernel<<<(int)((p3 + 255)/256), 256>>>(s_w_hid, t_w_hid);
        int p4 = NB*NHID*2*HD;
        pack_bhid_kernel<<<(p4 + 255)/256, 256>>>(s_b_hid, t_b_hid);
    }
    tcg(ev, EVLD, 0, wk, b_key, keys, KVROWS, HD, EVLD, DIN, 0, 0,
        (long long)DIN*HD, HD, (long long)KVROWS*HD, LL);
    tcg(ev, EVLD, 0, wv, b_val, vals, KVROWS, HD, EVLD, DIN, 0, 0,
        (long long)DIN*HD, HD, (long long)KVROWS*HD, LL);
    tcg(attin, 384, 0, wshift, b_shift, attv, ROWS, HD, 384, 384, 0, 0, 0, 0, 0, 1);
    for (int l = 0; l < LL; l++) {
        attn_kernel<<<dim3(BNB, HH), 256>>>(attv,
            keys + (long long)l*KVROWS*HD,
            vals + (long long)l*KVROWS*HD, attbuf);
        add_ln_kernel<<<ROWS, 256>>>(attv, attbuf, ln1_s + l*HD, ln1_b + l*HD);
        tcg(attv, HD, 0, ffw1 + (long long)l*HD*HD, ff_b1 + l*HD, f1,
            ROWS, HD, HD, HD, 1, 1, 0, 0, 0, 1);
        tcg(f1, HD, 0, ffw2 + (long long)l*HD*HD, ff_b2 + l*HD, f2,
            ROWS, HD, HD, HD, 0, 0, 0, 0, 0, 1);
        add_ln_kernel<<<ROWS, 256>>>(attv, f2, ln2_s + l*HD, ln2_b + l*HD);
    }
    {
        int n = ROWS*VV;
        init_flow_kernel<<<(n + 255)/256, 256>>>(true_value);
        int n2 = ROWS*INLD;
        copy_y_kernel<<<(n2 + 255)/256, 256>>>();
        write_mu_kernel<<<(n + 255)/256, 256>>>(0);
    }
    const long long perW = (long long)CY*HD;
    const long long perH = (long long)HD*HD;
    const long long sCh  = (long long)ROWS*HD;
    for (int blk = 0; blk < NB; blk++) {
        tcg(inp, INLD, 0, win + (long long)blk*2*perW, bin + (long long)blk*2*HD, hA,
            ROWS, HD, INLD, CY, 2, 1, perW, HD, sCh, 2);
        float* bufs[5] = {hA, hB, hA, hB, hA};
        for (int i = 0; i < NHID; i++) {
            long long wo = ((long long)(blk*NHID + i))*2;
            tcg(bufs[i], HD, sCh, whid + wo*perH, bhid + wo*HD, bufs[i+1],
                ROWS, HD, HD, HD, 2, 1, perH, HD, sCh, 2);
        }
        out3_coupling_kernel<<<(ROWS*32 + 255)/256, 256>>>(bufs[NHID],
            s_w_out + (long long)blk*HD*VV, s_b_out + blk*VV,
            t_w_out + (long long)blk*HD*VV, t_b_out + blk*VV, blk);
        bn_stats_kernel<<<T2*VV, 256>>>();
        {
            int n = ROWS*VV;
            bn_apply_kernel<<<(n + 255)/256, 256>>>(bn_lg, bn_be, blk, blk + 1 < NB);
        }
    }
    final_kernel<<<(BNB + 255)/256, 256>>>(out);
}

// round 8
// speedup vs baseline: 2.1590x; 2.1590x over previous
#include <cuda_runtime.h>
#include <cuda_fp16.h>
#include <mma.h>
#include <cstdint>
#include <math.h>

using namespace nvcuda;

// ---------------- problem constants ----------------
#define BNB   650
#define TT    48
#define T2    12
#define VV    3
#define CC    128
#define DIN   387
#define EVLD  416          // padded ev stride (mult of 32, 16B-aligned half rows)
#define HD    512
#define HH    8
#define DD    64
#define LL    4
#define NB    6
#define NHID  4
#define CY    515
#define INLD  544          // padded inp stride (mult of 32)
#define ROWS  (BNB*T2)     // 7800
#define KVROWS (BNB*TT)    // 31200
#define LOG2PI 1.8378770664093453f

// ---------------- scratch ----------------
__device__ __half g_ev[BNB*TT*EVLD];
__device__ __half g_wk[LL*DIN*HD];
__device__ __half g_wv[LL*DIN*HD];
__device__ __half g_wshift[384*HD];
__device__ __half g_ffw1[LL*HD*HD];
__device__ __half g_ffw2[LL*HD*HD];
__device__ __half g_keys[LL*KVROWS*HD];
__device__ __half g_vals[LL*KVROWS*HD];
__device__ __half g_attin[ROWS*384];
__device__ __half g_attv[ROWS*HD];
__device__ __half g_attbuf[ROWS*HD];
__device__ __half g_f1[ROWS*HD];
__device__ __half g_f2[ROWS*HD];
__device__ __half g_inp[ROWS*INLD];
__device__ __half g_hA[2*ROWS*HD];
__device__ __half g_hB[2*ROWS*HD];
__device__ __half g_win[NB*2*CY*HD];
__device__ __half g_whid[NB*NHID*2*HD*HD];
__device__ float g_bin[NB*2*HD];
__device__ float g_bhid[NB*NHID*2*HD];
__device__ float g_u[ROWS*VV];
__device__ float g_ld[ROWS*VV];
__device__ float g_stats[2*T2*VV];

__device__ __forceinline__ float fast_tanh(float x) {
    float y;
    asm("tanh.approx.f32 %0, %1;" : "=f"(y) : "f"(x));
    return y;
}
__device__ __forceinline__ float epi_act(float v, int act) {
    if (act == 1) return fmaxf(v, 0.f);
    if (act == 2) return fast_tanh(v);
    return v;
}
__device__ __forceinline__ void cpa16(uint32_t dst, const void* src, int sz) {
    asm volatile("cp.async.cg.shared.global [%0], [%1], 16, %2;"
                 :: "r"(dst), "l"(src), "r"(sz));
}
__device__ __forceinline__ void cpa_commit() {
    asm volatile("cp.async.commit_group;" ::: "memory");
}

// ---------- wmma fp16 GEMM: 128 thr, CTA 128x128, 4 warps of 64x64 --------
// 3-stage cp.async pipeline; C staged through SMEM (float) for fused epilogue.
#define ALD 40                        // halves; 80B rows (16B-mult)
#define BLD 136                       // halves; 272B rows
#define A_STG (128*ALD)               // 5120 halves
#define B_STG (32*BLD)                // 4352 halves
#define STG   (A_STG + B_STG)         // 9472 halves = 18944 B
#define NSTAGE 3
#define CLD 132
#define WM_SMEM (128*CLD*4)           // 67584 B (covers 3*STG*2 = 56832 B too)

__global__ __launch_bounds__(128, 2) void wmma_gemm(
    const __half* __restrict__ A, int lda, long long sA,
    const __half* __restrict__ B, const float* __restrict__ bias,
    __half* __restrict__ C,
    int M, int N, int Kpad, int Kreal, int act0, int act1,
    long long sB, long long sBias, long long sC)
{
    extern __shared__ float smf[];
    __half* smh = (__half*)smf;
    long long z = blockIdx.z;
    A    += z * sA;
    B    += z * sB;
    bias += z * sBias;
    C    += z * sC;
    int act = (z == 0) ? act0 : act1;

    int bm = blockIdx.x * 128, bn = blockIdx.y * 128;
    int tid = threadIdx.x, wid = tid >> 5;
    int warp_m = wid >> 1, warp_n = wid & 1;   // 2x2 warps of 64x64

    wmma::fragment<wmma::accumulator, 16, 16, 16, float> acc[4][4];
    #pragma unroll
    for (int i = 0; i < 4; i++)
        #pragma unroll
        for (int j = 0; j < 4; j++) wmma::fill_fragment(acc[i][j], 0.f);

    int nch = Kpad >> 5;               // Kpad is a multiple of 32

    auto load_stage = [&](int s, int c) {
        uint32_t base = (uint32_t)__cvta_generic_to_shared(smh + s * STG);
        uint32_t bBase = base + A_STG * 2;
        int k0 = c << 5;
        // A: 128 rows x 32 halves = 512 x 16B
        #pragma unroll
        for (int it = 0; it < 4; it++) {
            int q = it * 128 + tid;
            int r = q >> 2, kk = (q & 3) << 3;
            int gm = bm + r, gk = k0 + kk;
            int ok = (gm < M);
            int cgm = ok ? gm : 0;
            cpa16(base + (uint32_t)(r * ALD + kk) * 2,
                  A + (long long)cgm * lda + gk, ok ? 16 : 0);
        }
        // B: 32 rows x 128 halves = 512 x 16B
        #pragma unroll
        for (int it = 0; it < 4; it++) {
            int q = it * 128 + tid;
            int kk = q >> 4, n = (q & 15) << 3;
            int gk = k0 + kk;
            int ok = (gk < Kreal);
            int cgk = ok ? gk : 0;
            cpa16(bBase + (uint32_t)(kk * BLD + n) * 2,
                  B + (long long)cgk * N + bn + n, ok ? 16 : 0);
        }
    };

    load_stage(0, 0);
    cpa_commit();
    if (nch > 1) { load_stage(1, 1); cpa_commit(); }

    for (int c = 0; c < nch; c++) {
        if (c + 1 < nch) asm volatile("cp.async.wait_group 1;" ::: "memory");
        else             asm volatile("cp.async.wait_group 0;" ::: "memory");
        __syncthreads();
        if (c + 2 < nch) { load_stage((c + 2) % NSTAGE, c + 2); cpa_commit(); }

        __half* As = smh + (c % NSTAGE) * STG;
        __half* Bs = As + A_STG;
        #pragma unroll
        for (int ks = 0; ks < 2; ks++) {
            int k0 = ks * 16;
            wmma::fragment<wmma::matrix_a, 16, 16, 16, __half, wmma::row_major> af[4];
            wmma::fragment<wmma::matrix_b, 16, 16, 16, __half, wmma::row_major> bf[4];
            #pragma unroll
            for (int i = 0; i < 4; i++)
                wmma::load_matrix_sync(af[i], As + (warp_m*64 + i*16) * ALD + k0, ALD);
            #pragma unroll
            for (int j = 0; j < 4; j++)
                wmma::load_matrix_sync(bf[j], Bs + k0 * BLD + warp_n*64 + j*16, BLD);
            #pragma unroll
            for (int i = 0; i < 4; i++)
                #pragma unroll
                for (int j = 0; j < 4; j++)
                    wmma::mma_sync(acc[i][j], af[i], bf[j], acc[i][j]);
        }
    }
    __syncthreads();

    float* Cs = smf;
    #pragma unroll
    for (int i = 0; i < 4; i++)
        #pragma unroll
        for (int j = 0; j < 4; j++)
            wmma::store_matrix_sync(Cs + (warp_m*64 + i*16) * CLD + warp_n*64 + j*16,
                                    acc[i][j], CLD, wmma::mem_row_major);
    __syncthreads();

    #pragma unroll
    for (int it = 0; it < 32; it++) {
        int idx = it * 128 + tid;
        int r = idx >> 5, c4 = (idx & 31) * 4;
        int gm = bm + r;
        if (gm >= M) continue;
        int gc = bn + c4;
        float vx = epi_act(Cs[r * CLD + c4 + 0] + bias[gc + 0], act);
        float vy = epi_act(Cs[r * CLD + c4 + 1] + bias[gc + 1], act);
        float vz = epi_act(Cs[r * CLD + c4 + 2] + bias[gc + 2], act);
        float vw = epi_act(Cs[r * CLD + c4 + 3] + bias[gc + 3], act);
        __half2* cp = (__half2*)(C + (long long)gm * N + gc);
        cp[0] = __floats2half2_rn(vx, vy);
        cp[1] = __floats2half2_rn(vz, vw);
    }
}

// ---------------- pack / convert kernels ----------------
__global__ void halfcopy_kernel(const float* __restrict__ src, __half* __restrict__ dst,
                                long long n)
{
    long long idx = (long long)blockIdx.x * blockDim.x + threadIdx.x;
    if (idx < n) dst[idx] = __float2half(src[idx]);
}
__global__ void pack_win_kernel(const float* __restrict__ s, const float* __restrict__ t)
{
    int idx = blockIdx.x * blockDim.x + threadIdx.x;
    const int per = CY*HD;
    if (idx >= NB*2*per) return;
    int blk = idx / (2*per);
    int r = idx - blk*2*per;
    int net = r / per, off = r - net*per;
    g_win[idx] = __float2half(net ? t[(long long)blk*per + off] : s[(long long)blk*per + off]);
}
__global__ void pack_bin_kernel(const float* __restrict__ s, const float* __restrict__ t)
{
    int idx = blockIdx.x * blockDim.x + threadIdx.x;
    if (idx >= NB*2*HD) return;
    int blk = idx / (2*HD);
    int r = idx - blk*2*HD;
    int net = r / HD, off = r - net*HD;
    g_bin[idx] = net ? t[blk*HD + off] : s[blk*HD + off];
}
__global__ void pack_whid_kernel(const float* __restrict__ s, const float* __restrict__ t)
{
    long long idx = (long long)blockIdx.x * blockDim.x + threadIdx.x;
    const long long per = HD*HD;
    if (idx >= (long long)NB*NHID*2*per) return;
    long long u = idx / (2*per);
    long long r = idx - u*2*per;
    int net = (int)(r / per);
    long long off = r - (long long)net*per;
    g_whid[idx] = __float2half(net ? t[u*per + off] : s[u*per + off]);
}
__global__ void pack_bhid_kernel(const float* __restrict__ s, const float* __restrict__ t)
{
    int idx = blockIdx.x * blockDim.x + threadIdx.x;
    if (idx >= NB*NHID*2*HD) return;
    int u = idx / (2*HD);
    int r = idx - u*2*HD;
    int net = r / HD, off = r - net*HD;
    g_bhid[idx] = net ? t[u*HD + off] : s[u*HD + off];
}

// ---------------- small kernels ----------------
__global__ void transpose_w_kernel(const float* __restrict__ W, __half* __restrict__ out)
{
    int idx = blockIdx.x * blockDim.x + threadIdx.x;
    if (idx >= LL*DIN*HD) return;
    int l = idx / (DIN*HD);
    int rem = idx - l * (DIN*HD);
    int e = rem / HD;
    int n = rem - e * HD;
    int h = n >> 6, d = n & 63;
    out[idx] = __float2half(W[(((long long)l*HH + h)*DIN + e)*DD + d]);
}

__global__ void build_ev_kernel(const float* __restrict__ encoded,
                                const float* __restrict__ tv)
{
    int idx = blockIdx.x * blockDim.x + threadIdx.x;
    if (idx >= BNB*TT*EVLD) return;
    int bn = idx / (TT*EVLD);
    int rem = idx - bn * (TT*EVLD);
    int t = rem / EVLD;
    int e = rem - t * EVLD;
    float val = 0.f;
    if (e < DIN) {
        int v = e / (CC+1);
        int j = e - v * (CC+1);
        if (j < CC) val = encoded[(((long long)bn*VV + v)*TT + t)*CC + j];
        else        val = tv[((long long)bn*VV + v)*TT + t];
    }
    g_ev[idx] = __float2half(val);
}

__global__ void build_attin_kernel(const float* __restrict__ encoded)
{
    int idx = blockIdx.x * blockDim.x + threadIdx.x;
    if (idx >= ROWS*384) return;
    int row = idx / 384;
    int col = idx - row*384;
    int bn = row / T2, t2 = row - bn*T2;
    int v = col >> 7, j = col & 127;
    g_attin[idx] = __float2half(encoded[(((long long)bn*VV + v)*TT + (TT - T2 + t2))*CC + j]);
}

__global__ void attn_kernel(const __half* __restrict__ attv,
                            const __half* __restrict__ keys_l,
                            const __half* __restrict__ vals_l,
                            __half* __restrict__ attbuf)
{
    int bn = blockIdx.x, h = blockIdx.y;
    __shared__ float Qs[T2*DD];
    __shared__ float Ks[TT*DD];
    __shared__ float Vs[TT*DD];
    __shared__ float Ss[T2*TT];
    int tid = threadIdx.x;
    const __half* kb = keys_l + (long long)bn*TT*HD + h*DD;
    const __half* vb = vals_l + (long long)bn*TT*HD + h*DD;
    for (int i = tid; i < TT*DD; i += 256) {
        int t = i >> 6, d = i & 63;
        Ks[i] = __half2float(kb[(long long)t*HD + d]);
        Vs[i] = __half2float(vb[(long long)t*HD + d]);
    }
    for (int i = tid; i < T2*DD; i += 256) {
        int v = i >> 6, d = i & 63;
        Qs[i] = __half2float(attv[((long long)bn*T2 + v)*HD + h*DD + d]);
    }
    __syncthreads();
    const float scale = 0.125f;
    for (int i = tid; i < T2*TT; i += 256) {
        int v = i / TT, w = i - v*TT;
        float s;
        if (w >= (TT - T2) + v) s = -INFINITY;
        else {
            float a = 0.f;
            #pragma unroll
            for (int d = 0; d < DD; d++) a += Qs[v*DD+d] * Ks[w*DD+d];
            s = a * scale;
        }
        Ss[i] = s;
    }
    __syncthreads();
    if (tid < T2) {
        int v = tid;
        float m = -INFINITY;
        for (int w = 0; w < TT; w++) m = fmaxf(m, Ss[v*TT+w]);
        float sum = 0.f;
        for (int w = 0; w < TT; w++) {
            float e = expf(Ss[v*TT+w] - m);
            Ss[v*TT+w] = e; sum += e;
        }
        float inv = 1.f / sum;
        for (int w = 0; w < TT; w++) Ss[v*TT+w] *= inv;
    }
    __syncthreads();
    for (int i = tid; i < T2*DD; i += 256) {
        int v = i >> 6, d = i & 63;
        float a = 0.f;
        #pragma unroll
        for (int w = 0; w < TT; w++) a += Ss[v*TT+w] * Vs[w*DD+d];
        attbuf[((long long)bn*T2 + v)*HD + h*DD + d] = __float2half(a);
    }
}

__global__ void add_ln_kernel(__half* __restrict__ x, const __half* __restrict__ r,
                              const float* __restrict__ g, const float* __restrict__ b)
{
    int row = blockIdx.x;
    int tid = threadIdx.x;
    __shared__ float red[256];
    long long base = (long long)row * HD;
    float v0 = __half2float(x[base + tid])       + __half2float(r[base + tid]);
    float v1 = __half2float(x[base + tid + 256]) + __half2float(r[base + tid + 256]);
    red[tid] = v0 + v1;
    __syncthreads();
    for (int s = 128; s > 0; s >>= 1) { if (tid < s) red[tid] += red[tid+s]; __syncthreads(); }
    float mean = red[0] * (1.f/512.f);
    __syncthreads();
    float d0 = v0 - mean, d1 = v1 - mean;
    red[tid] = d0*d0 + d1*d1;
    __syncthreads();
    for (int s = 128; s > 0; s >>= 1) { if (tid < s) red[tid] += red[tid+s]; __syncthreads(); }
    float rstd = rsqrtf(red[0] * (1.f/512.f) + 1e-5f);
    x[base + tid]       = __float2half(d0 * rstd * g[tid]       + b[tid]);
    x[base + tid + 256] = __float2half(d1 * rstd * g[tid + 256] + b[tid + 256]);
}

__global__ void init_flow_kernel(const float* __restrict__ tv)
{
    int idx = blockIdx.x * blockDim.x + threadIdx.x;
    if (idx >= ROWS*VV) return;
    int bn = idx / (T2*VV);
    int rem = idx - bn * (T2*VV);
    int t2 = rem / VV, v = rem - t2*VV;
    g_u[idx] = tv[((long long)bn*VV + v)*TT + (TT - T2 + t2)];
    g_ld[idx] = 0.f;
}

__global__ void copy_y_kernel()
{
    int idx = blockIdx.x * blockDim.x + threadIdx.x;
    if (idx >= ROWS*INLD) return;
    int row = idx / INLD, col = idx - row*INLD;
    if (col < HD)       g_inp[idx] = g_attv[(long long)row*HD + col];
    else if (col >= HD + VV) g_inp[idx] = __float2half(0.f);
    // cols 512..514 written by write_mu / bn_apply
}

__global__ void write_mu_kernel(int blk)
{
    int idx = blockIdx.x * blockDim.x + threadIdx.x;
    if (idx >= ROWS*VV) return;
    int row = idx / VV, v = idx - row*VV;
    float mask = (float)((v + blk) & 1);
    g_inp[(long long)row * INLD + HD + v] = __float2half(g_u[idx] * mask);
}

__global__ void out3_coupling_kernel(const __half* __restrict__ h,
                                     const float* __restrict__ Ws, const float* __restrict__ bs,
                                     const float* __restrict__ Wt, const float* __restrict__ bt,
                                     int blk)
{
    int gw = (blockIdx.x * blockDim.x + threadIdx.x) >> 5;
    int lane = threadIdx.x & 31;
    if (gw >= ROWS) return;
    const __half* as = h + (long long)gw * HD;
    const __half* at = h + (long long)ROWS*HD + (long long)gw * HD;
    float s0 = 0.f, s1 = 0.f, s2 = 0.f, t0 = 0.f, t1 = 0.f, t2 = 0.f;
    for (int k = lane; k < HD; k += 32) {
        float av = __half2float(as[k]), bv = __half2float(at[k]);
        s0 += av * Ws[k*3 + 0]; s1 += av * Ws[k*3 + 1]; s2 += av * Ws[k*3 + 2];
        t0 += bv * Wt[k*3 + 0]; t1 += bv * Wt[k*3 + 1]; t2 += bv * Wt[k*3 + 2];
    }
    #pragma unroll
    for (int off = 16; off > 0; off >>= 1) {
        s0 += __shfl_down_sync(0xffffffffu, s0, off);
        s1 += __shfl_down_sync(0xffffffffu, s1, off);
        s2 += __shfl_down_sync(0xffffffffu, s2, off);
        t0 += __shfl_down_sync(0xffffffffu, t0, off);
        t1 += __shfl_down_sync(0xffffffffu, t1, off);
        t2 += __shfl_down_sync(0xffffffffu, t2, off);
    }
    if (lane == 0) {
        float sv[3] = {s0 + bs[0], s1 + bs[1], s2 + bs[2]};
        float tv[3] = {t0 + bt[0], t1 + bt[1], t2 + bt[2]};
        #pragma unroll
        for (int v = 0; v < VV; v++) {
            if (((v + blk) & 1) == 0) {
                int idx = gw*3 + v;
                float s = sv[v];
                g_u[idx]  = (g_u[idx] - tv[v]) * expf(-s);
                g_ld[idx] -= s;
            }
        }
    }
}

__global__ void bn_stats_kernel()
{
    int col = blockIdx.x;
    int tid = threadIdx.x;
    __shared__ float rs[256], rq[256];
    float s = 0.f, q = 0.f;
    for (int bn = tid; bn < BNB; bn += 256) {
        float v = g_u[bn*(T2*VV) + col];
        s += v; q += v*v;
    }
    rs[tid] = s; rq[tid] = q;
    __syncthreads();
    for (int st = 128; st > 0; st >>= 1) {
        if (tid < st) { rs[tid] += rs[tid+st]; rq[tid] += rq[tid+st]; }
        __syncthreads();
    }
    if (tid == 0) {
        float m = rs[0] / (float)BNB;
        float var = rq[0] / (float)BNB - m*m;
        g_stats[col] = m;
        g_stats[T2*VV + col] = fmaxf(var, 0.f);
    }
}

__global__ void bn_apply_kernel(const float* __restrict__ lg,
                                const float* __restrict__ beta, int blk, int write_next)
{
    int idx = blockIdx.x * blockDim.x + threadIdx.x;
    if (idx >= ROWS*VV) return;
    int col = idx % (T2*VV);
    int v = idx % VV;
    float m = g_stats[col];
    float var = g_stats[T2*VV + col];
    float gg = lg[blk*VV + v];
    float be = beta[blk*VV + v];
    float r = rsqrtf(var + 1e-5f);
    float u = expf(gg) * (g_u[idx] - m) * r + be;
    g_u[idx] = u;
    g_ld[idx] += gg - 0.5f * logf(var + 1e-5f);
    if (write_next) {
        float mask = (float)((v + blk + 1) & 1);
        g_inp[(long long)(idx / VV) * INLD + HD + v] = __float2half(u * mask);
    }
}

__global__ void final_kernel(float* __restrict__ out)
{
    int bn = blockIdx.x * blockDim.x + threadIdx.x;
    if (bn >= BNB) return;
    float acc = 0.f;
    #pragma unroll
    for (int i = 0; i < T2*VV; i++) {
        float u = g_u[bn*(T2*VV) + i];
        acc += 0.5f*u*u + 0.5f*LOG2PI - g_ld[bn*(T2*VV) + i];
    }
    out[bn] = acc;
}

// ---------------- host launcher ----------------
static inline void tcg(const __half* A, int lda, long long sA,
                       const __half* B, const float* bias, __half* C,
                       int M, int N, int Kpad, int Kreal, int act0, int act1,
                       long long sB, long long sBias, long long sC, int Z)
{
    dim3 grid((M + 127)/128, N/128, Z);
    wmma_gemm<<<grid, 128, WM_SMEM>>>(A, lda, sA, B, bias, C,
                                      M, N, Kpad, Kreal, act0, act1, sB, sBias, sC);
}

extern "C" void kernel_launch(void* const* d_in, const int* in_sizes, int n_in,
                              void* d_out, int out_size)
{
    const float* encoded    = (const float*)d_in[0];
    const float* true_value = (const float*)d_in[1];
    const float* W_shift    = (const float*)d_in[2];
    const float* b_shift    = (const float*)d_in[3];
    const float* W_key      = (const float*)d_in[4];
    const float* b_key      = (const float*)d_in[5];
    const float* W_val      = (const float*)d_in[6];
    const float* b_val      = (const float*)d_in[7];
    const float* ln1_s      = (const float*)d_in[8];
    const float* ln1_b      = (const float*)d_in[9];
    const float* ff_w1      = (const float*)d_in[10];
    const float* ff_b1      = (const float*)d_in[11];
    const float* ff_w2      = (const float*)d_in[12];
    const float* ff_b2      = (const float*)d_in[13];
    const float* ln2_s      = (const float*)d_in[14];
    const float* ln2_b      = (const float*)d_in[15];
    const float* s_w_in     = (const float*)d_in[16];
    const float* s_b_in     = (const float*)d_in[17];
    const float* s_w_hid    = (const float*)d_in[18];
    const float* s_b_hid    = (const float*)d_in[19];
    const float* s_w_out    = (const float*)d_in[20];
    const float* s_b_out    = (const float*)d_in[21];
    const float* t_w_in     = (const float*)d_in[22];
    const float* t_b_in     = (const float*)d_in[23];
    const float* t_w_hid    = (const float*)d_in[24];
    const float* t_b_hid    = (const float*)d_in[25];
    const float* t_w_out    = (const float*)d_in[26];
    const float* t_b_out    = (const float*)d_in[27];
    const float* bn_lg      = (const float*)d_in[28];
    const float* bn_be      = (const float*)d_in[29];
    float* out = (float*)d_out;

    cudaFuncSetAttribute(wmma_gemm, cudaFuncAttributeMaxDynamicSharedMemorySize, WM_SMEM);

    __half *ev, *wk, *wv, *wshift, *ffw1, *ffw2, *keys, *vals, *attin, *attv, *attbuf;
    __half *f1, *f2, *inp, *hA, *hB, *win, *whid;
    float *bin, *bhid;
    cudaGetSymbolAddress((void**)&ev,     g_ev);
    cudaGetSymbolAddress((void**)&wk,     g_wk);
    cudaGetSymbolAddress((void**)&wv,     g_wv);
    cudaGetSymbolAddress((void**)&wshift, g_wshift);
    cudaGetSymbolAddress((void**)&ffw1,   g_ffw1);
    cudaGetSymbolAddress((void**)&ffw2,   g_ffw2);
    cudaGetSymbolAddress((void**)&keys,   g_keys);
    cudaGetSymbolAddress((void**)&vals,   g_vals);
    cudaGetSymbolAddress((void**)&attin,  g_attin);
    cudaGetSymbolAddress((void**)&attv,   g_attv);
    cudaGetSymbolAddress((void**)&attbuf, g_attbuf);
    cudaGetSymbolAddress((void**)&f1,     g_f1);
    cudaGetSymbolAddress((void**)&f2,     g_f2);
    cudaGetSymbolAddress((void**)&inp,    g_inp);
    cudaGetSymbolAddress((void**)&hA,     g_hA);
    cudaGetSymbolAddress((void**)&hB,     g_hB);
    cudaGetSymbolAddress((void**)&win,    g_win);
    cudaGetSymbolAddress((void**)&whid,   g_whid);
    cudaGetSymbolAddress((void**)&bin,    g_bin);
    cudaGetSymbolAddress((void**)&bhid,   g_bhid);

    {
        int n = LL*DIN*HD;
        transpose_w_kernel<<<(n + 255)/256, 256>>>(W_key, wk);
        transpose_w_kernel<<<(n + 255)/256, 256>>>(W_val, wv);
        long long nw = 384*HD;
        halfcopy_kernel<<<(int)((nw + 255)/256), 256>>>(W_shift, wshift, nw);
        long long nf = (long long)LL*HD*HD;
        halfcopy_kernel<<<(int)((nf + 255)/256), 256>>>(ff_w1, ffw1, nf);
        halfcopy_kernel<<<(int)((nf + 255)/256), 256>>>(ff_w2, ffw2, nf);
        int m = BNB*TT*EVLD;
        build_ev_kernel<<<(m + 255)/256, 256>>>(encoded, true_value);
        int q = ROWS*384;
        build_attin_kernel<<<(q + 255)/256, 256>>>(encoded);
        int p1 = NB*2*CY*HD;
        pack_win_kernel<<<(p1 + 255)/256, 256>>>(s_w_in, t_w_in);
        int p2 = NB*2*HD;
        pack_bin_kernel<<<(p2 + 255)/256, 256>>>(s_b_in, t_b_in);
        long long p3 = (long long)NB*NHID*2*HD*HD;
        pack_whid_kernel<<<(int)((p3 + 255)/256), 256>>>(s_w_hid, t_w_hid);
        int p4 = NB*NHID*2*HD;
        pack_bhid_kernel<<<(p4 + 255)/256, 256>>>(s_b_hid, t_b_hid);
    }
    tcg(ev, EVLD, 0, wk, b_key, keys, KVROWS, HD, EVLD, DIN, 0, 0,
        (long long)DIN*HD, HD, (long long)KVROWS*HD, LL);
    tcg(ev, EVLD, 0, wv, b_val, vals, KVROWS, HD, EVLD, DIN, 0, 0,
        (long long)DIN*HD, HD, (long long)KVROWS*HD, LL);
    tcg(attin, 384, 0, wshift, b_shift, attv, ROWS, HD, 384, 384, 0, 0, 0, 0, 0, 1);
    for (int l = 0; l < LL; l++) {
        attn_kernel<<<dim3(BNB, HH), 256>>>(attv,
            keys + (long long)l*KVROWS*HD,
            vals + (long long)l*KVROWS*HD, attbuf);
        add_ln_kernel<<<ROWS, 256>>>(attv, attbuf, ln1_s + l*HD, ln1_b + l*HD);
        tcg(attv, HD, 0, ffw1 + (long long)l*HD*HD, ff_b1 + l*HD, f1,
            ROWS, HD, HD, HD, 1, 1, 0, 0, 0, 1);
        tcg(f1, HD, 0, ffw2 + (long long)l*HD*HD, ff_b2 + l*HD, f2,
            ROWS, HD, HD, HD, 0, 0, 0, 0, 0, 1);
        add_ln_kernel<<<ROWS, 256>>>(attv, f2, ln2_s + l*HD, ln2_b + l*HD);
    }
    {
        int n = ROWS*VV;
        init_flow_kernel<<<(n + 255)/256, 256>>>(true_value);
        int n2 = ROWS*INLD;
        copy_y_kernel<<<(n2 + 255)/256, 256>>>();
        write_mu_kernel<<<(n + 255)/256, 256>>>(0);
    }
    const long long perW = (long long)CY*HD;
    const long long perH = (long long)HD*HD;
    const long long sCh  = (long long)ROWS*HD;
    for (int blk = 0; blk < NB; blk++) {
        tcg(inp, INLD, 0, win + (long long)blk*2*perW, bin + (long long)blk*2*HD, hA,
            ROWS, HD, INLD, CY, 2, 1, perW, HD, sCh, 2);
        __half* bufs[5] = {hA, hB, hA, hB, hA};
        for (int i = 0; i < NHID; i++) {
            long long wo = ((long long)(blk*NHID + i))*2;
            tcg(bufs[i], HD, sCh, whid + wo*perH, bhid + wo*HD, bufs[i+1],
                ROWS, HD, HD, HD, 2, 1, perH, HD, sCh, 2);
        }
        out3_coupling_kernel<<<(ROWS*32 + 255)/256, 256>>>(bufs[NHID],
            s_w_out + (long long)blk*HD*VV, s_b_out + blk*VV,
            t_w_out + (long long)blk*HD*VV, t_b_out + blk*VV, blk);
        bn_stats_kernel<<<T2*VV, 256>>>();
        {
            int n = ROWS*VV;
            bn_apply_kernel<<<(n + 255)/256, 256>>>(bn_lg, bn_be, blk, blk + 1 < NB);
        }
    }
    final_kernel<<<(BNB + 255)/256, 256>>>(out);
}